// round 8
// baseline (speedup 1.0000x reference)
#include <cuda_runtime.h>

#define EPSV 1e-5f
typedef unsigned long long ull;

// ---------------- shared memory layout (float offsets), 14336 floats = 56KB --
// Phase 1:
//   [0,7168)      pooled[128][56]
//     after stage B (pooled dead): QT[4][60]@0, KT[4][60]@240, VT[56][32]@480,
//                                  S[56][60]@2272..5632, attnT[56][60]@5632..8992
//                                  RED@8992..9024
//   [7168,11392)  wcrT[128][33]   (dead after stage B)
//   [11392,12416) vTw[32][32]
//   [12416,14336) xbuf[32][60]
// Phase 2:
//   [0,3456)      xpadA[32][9][12]
//   [3456,5760)   shA[32][9][8]  (later aliased by shB after a sync)
//   [5760,9216)   xpadB[32][9][12]
//   [9216,13968)  wres half [144][33]=4752 ; later w1T 2x[144][17]=4896
//   [14112,14256) w2
#define POOL_OFF 0
#define QT_OFF   0
#define KT_OFF   240
#define VT_OFF   480
#define S_OFF    2272
#define ATT_OFF  5632
#define RED_OFF  8992
#define WCRT_OFF 7168
#define VTW_OFF  11392
#define XBUF_OFF 12416

#define XPA_OFF  0
#define SHA_OFF  3456
#define XPB_OFF  5760
#define SHB_OFF  3456
#define WR2_OFF  9216
#define W2_OFF   14112
#define SMEM_FLOATS 14336

// ---------------- packed f32x2 helpers ----------------
__device__ __forceinline__ ull pk2(float x, float y) {
    ull r; asm("mov.b64 %0, {%1, %2};" : "=l"(r) : "f"(x), "f"(y)); return r;
}
__device__ __forceinline__ void up2(ull v, float& x, float& y) {
    asm("mov.b64 {%0, %1}, %2;" : "=f"(x), "=f"(y) : "l"(v));
}
__device__ __forceinline__ ull fma2(ull a, ull b, ull c) {
    ull r; asm("fma.rn.f32x2 %0, %1, %2, %3;" : "=l"(r) : "l"(a), "l"(b), "l"(c)); return r;
}
__device__ __forceinline__ ull add2(ull a, ull b) {
    ull r; asm("add.rn.f32x2 %0, %1, %2;" : "=l"(r) : "l"(a), "l"(b)); return r;
}

// 8-wide GEMM step: acc[4] += w * x[0..7], x warp-uniform (broadcast LDS.128)
__device__ __forceinline__ void g8(ull acc[4], const float* __restrict__ x, float wv) {
    ulonglong2 A = *(const ulonglong2*)(x);
    ulonglong2 B = *(const ulonglong2*)(x + 4);
    ull wp = pk2(wv, wv);
    acc[0] = fma2(wp, A.x, acc[0]); acc[1] = fma2(wp, A.y, acc[1]);
    acc[2] = fma2(wp, B.x, acc[2]); acc[3] = fma2(wp, B.y, acc[3]);
}

// 3x3 conv over 16 input channels, output row p (8 cols), acc[4] f32x2 pairs.
__device__ __forceinline__ void conv16(ull acc[4], const float* __restrict__ xb,
                                       const float* __restrict__ sb,
                                       const float* __restrict__ wb, int ws,
                                       int o, int p) {
    #pragma unroll 2
    for (int ch = 0; ch < 16; ++ch) {
        #pragma unroll
        for (int r = 0; r < 3; ++r) {
            const float* row  = xb + ch * 108 + (p + r) * 12;
            const float* srow = sb + ch * 72 + (p + r) * 8;
            ulonglong2 E01 = *(const ulonglong2*)(row);       // x0..x3
            ulonglong2 E23 = *(const ulonglong2*)(row + 4);   // x4..x7
            ull        E4  = *(const ull*)(row + 8);          // x8,x9
            ulonglong2 O01 = *(const ulonglong2*)(srow);      // x1..x4
            ulonglong2 O23 = *(const ulonglong2*)(srow + 4);  // x5..x8
            const float* wp = wb + (ch * 9 + r * 3) * ws + o;
            float wv0 = wp[0], wv1 = wp[ws], wv2 = wp[2 * ws];
            ull w0 = pk2(wv0, wv0), w1 = pk2(wv1, wv1), w2 = pk2(wv2, wv2);
            acc[0] = fma2(w0, E01.x, acc[0]); acc[1] = fma2(w0, E01.y, acc[1]);
            acc[2] = fma2(w0, E23.x, acc[2]); acc[3] = fma2(w0, E23.y, acc[3]);
            acc[0] = fma2(w1, O01.x, acc[0]); acc[1] = fma2(w1, O01.y, acc[1]);
            acc[2] = fma2(w1, O23.x, acc[2]); acc[3] = fma2(w1, O23.y, acc[3]);
            acc[0] = fma2(w2, E01.y, acc[0]); acc[1] = fma2(w2, E23.x, acc[1]);
            acc[2] = fma2(w2, E23.y, acc[2]); acc[3] = fma2(w2, E4,    acc[3]);
        }
    }
}

__global__ void __launch_bounds__(256, 4) occ_fused_kernel(
    const float* __restrict__ mg,
    const float* __restrict__ w_cr, const float* __restrict__ b_cr,
    const float* __restrict__ bnr_w, const float* __restrict__ bnr_b,
    const float* __restrict__ bnr_m, const float* __restrict__ bnr_v,
    const float* __restrict__ q_w,  const float* __restrict__ q_b,
    const float* __restrict__ k_w,  const float* __restrict__ k_b,
    const float* __restrict__ v_w,  const float* __restrict__ v_b,
    const float* __restrict__ gamma,
    const float* __restrict__ ln_w, const float* __restrict__ ln_b,
    const float* __restrict__ w_res, const float* __restrict__ b_res,
    const float* __restrict__ bnres_w, const float* __restrict__ bnres_b,
    const float* __restrict__ bnres_m, const float* __restrict__ bnres_v,
    const float* __restrict__ w1,  const float* __restrict__ b1,
    const float* __restrict__ bn1_w, const float* __restrict__ bn1_b,
    const float* __restrict__ bn1_m, const float* __restrict__ bn1_v,
    const float* __restrict__ w2,  const float* __restrict__ b2,
    float* __restrict__ out)
{
    extern __shared__ float sm[];
    const int t = threadIdx.x;
    const int b = blockIdx.x;
    const int w = t >> 5;
    const int lane = t & 31;
    float* red = sm + RED_OFF;

    // ============ Stage A: adaptive pool 16x16 -> 7x8 + stage phase-1 weights ======
    {
        const float* in = mg + (size_t)b * 32768;
        int c = t / 56, s = t - c * 56;        // one division, then incremental
        for (int idx = t; idx < 7168; idx += 256) {
            int p = s >> 3, q = s & 7;
            int r0 = (p * 147) >> 6;                 // == (p*16)/7
            int r1 = ((p + 1) * 16 + 6) / 7;
            const float2* bp = (const float2*)(in + c * 256 + q * 2);
            float acc = 0.f;
            for (int r = r0; r < r1; ++r) { float2 v2 = bp[r * 8]; acc += v2.x + v2.y; }
            sm[POOL_OFF + idx] = acc * (0.5f / (float)(r1 - r0));
            s += 32; c += 4; if (s >= 56) { s -= 56; ++c; }
        }
        for (int idx = t; idx < 4096; idx += 256) {       // wcrT[c][o], stride 33
            int o = idx >> 7, cc = idx & 127;
            sm[WCRT_OFF + cc * 33 + o] = w_cr[idx];
        }
        for (int idx = t; idx < 1024; idx += 256) {       // vTw[in][o], stride 32
            int in2 = idx >> 5, o = idx & 31;             // conflict-free STS
            sm[VTW_OFF + in2 * 32 + o] = v_w[o * 32 + in2];
        }
    }
    __syncthreads();

    // ============ Stage B: 1x1 128->32 + BN + ReLU. warp=p, lane=o ============
    if (w < 7) {
        ull a[4] = {0,0,0,0};
        const float* xb = sm + POOL_OFF + w * 8;
        const float* wc = sm + WCRT_OFF + lane;
        #pragma unroll 4
        for (int c = 0; c < 128; ++c)
            g8(a, xb + c * 56, wc[c * 33]);
        float sc = bnr_w[lane] * rsqrtf(bnr_v[lane] + EPSV);
        float bi = fmaf(b_cr[lane], sc, bnr_b[lane] - bnr_m[lane] * sc);
        float r[8];
        up2(a[0],r[0],r[1]); up2(a[1],r[2],r[3]); up2(a[2],r[4],r[5]); up2(a[3],r[6],r[7]);
        float* dst = sm + XBUF_OFF + lane * 60 + w * 8;
        #pragma unroll
        for (int q = 0; q < 8; ++q) dst[q] = fmaxf(fmaf(r[q], sc, bi), 0.f);
    }
    __syncthreads();

    // ============ Stage C1: v (warps 0-6), q & k (warp 7, weights via gmem) =======
    if (w < 7) {
        float bias = v_b[lane];
        ull a[4]; a[0]=a[1]=a[2]=a[3]=pk2(bias,bias);
        const float* xb = sm + XBUF_OFF + w * 8;
        const float* wv2p = sm + VTW_OFF + lane;
        #pragma unroll 4
        for (int in2 = 0; in2 < 32; ++in2)
            g8(a, xb + in2 * 60, wv2p[in2 * 32]);
        float r[8];
        up2(a[0],r[0],r[1]); up2(a[1],r[2],r[3]); up2(a[2],r[4],r[5]); up2(a[3],r[6],r[7]);
        #pragma unroll
        for (int q = 0; q < 8; ++q) sm[VT_OFF + (w * 8 + q) * 32 + lane] = r[q];
    } else if (lane < 28) {
        int d = lane / 7, p = lane - d * 7;
        const float* xb = sm + XBUF_OFF + p * 8;
        #pragma unroll
        for (int pass = 0; pass < 2; ++pass) {
            const float* W = (pass ? k_w : q_w) + d * 32;
            float bias = pass ? k_b[d] : q_b[d];
            ull a[4]; a[0]=a[1]=a[2]=a[3]=pk2(bias,bias);
            for (int in2 = 0; in2 < 32; ++in2) g8(a, xb + in2 * 60, __ldg(W + in2));
            float r[8];
            up2(a[0],r[0],r[1]); up2(a[1],r[2],r[3]); up2(a[2],r[4],r[5]); up2(a[3],r[6],r[7]);
            float* dst = sm + (pass ? KT_OFF : QT_OFF) + d * 60 + p * 8;
            #pragma unroll
            for (int q = 0; q < 8; ++q) dst[q] = r[q];
        }
    }
    __syncthreads();

    // ============ Stage C2: S[i][j] = sum_d q[d][i] k[d][j] ============
    if (w < 7) {
        int i0 = w * 8;
        #pragma unroll
        for (int seg = 0; seg < 2; ++seg) {
            int j = seg * 32 + lane;
            if (j < 56) {
                ull a[4] = {0,0,0,0};
                #pragma unroll
                for (int d = 0; d < 4; ++d)
                    g8(a, sm + QT_OFF + d * 60 + i0, sm[KT_OFF + d * 60 + j]);
                float r[8];
                up2(a[0],r[0],r[1]); up2(a[1],r[2],r[3]); up2(a[2],r[4],r[5]); up2(a[3],r[6],r[7]);
                #pragma unroll
                for (int q = 0; q < 8; ++q) sm[S_OFF + (i0 + q) * 60 + j] = r[q];
            }
        }
    }
    __syncthreads();

    // ============ softmax rows, write transposed attnT[j][i] ============
    if (t < 56) {
        float* row = sm + S_OFF + t * 60;
        const float4* r4 = (const float4*)row;
        float m = -1e30f;
        #pragma unroll
        for (int k = 0; k < 14; ++k) {
            float4 vv = r4[k];
            m = fmaxf(m, fmaxf(fmaxf(vv.x, vv.y), fmaxf(vv.z, vv.w)));
        }
        float ssum = 0.f;
        #pragma unroll 8
        for (int j = 0; j < 56; ++j) { float e = __expf(row[j] - m); row[j] = e; ssum += e; }
        float inv = 1.f / ssum;
        #pragma unroll 8
        for (int j = 0; j < 56; ++j) sm[ATT_OFF + j * 60 + t] = row[j] * inv;
    }
    __syncthreads();

    // ============ Stage C3: out[c][i] = sum_j v[j][c]*attnT[j][i]; x += gamma*out ==
    if (w < 7) {
        int i0 = w * 8;
        ull a[4] = {0,0,0,0};
        #pragma unroll 4
        for (int j = 0; j < 56; ++j)
            g8(a, sm + ATT_OFF + j * 60 + i0, sm[VT_OFF + j * 32 + lane]);
        float r[8];
        up2(a[0],r[0],r[1]); up2(a[1],r[2],r[3]); up2(a[2],r[4],r[5]); up2(a[3],r[6],r[7]);
        float g = gamma[0];
        float* xr = sm + XBUF_OFF + lane * 60 + i0;
        #pragma unroll
        for (int q = 0; q < 8; ++q) xr[q] = fmaf(g, r[q], xr[q]);
    }
    __syncthreads();

    // ============ Stage D: LayerNorm over 1792 (vals bridge xbuf -> xpadA) ========
    float vals[7];
    {
        float s1 = 0.f, s2 = 0.f;
        int c = t / 56, s = t - c * 56;
        #pragma unroll
        for (int k = 0; k < 7; ++k) {
            float x = sm[XBUF_OFF + c * 60 + s];
            vals[k] = x; s1 += x; s2 = fmaf(x, x, s2);
            s += 32; c += 4; if (s >= 56) { s -= 56; ++c; }
        }
        #pragma unroll
        for (int off = 16; off; off >>= 1) {
            s1 += __shfl_xor_sync(0xffffffffu, s1, off);
            s2 += __shfl_xor_sync(0xffffffffu, s2, off);
        }
        if (lane == 0) { red[w] = s1; red[8 + w] = s2; }
        __syncthreads();
        if (t == 0) {
            float S1 = 0.f, S2 = 0.f;
            for (int k = 0; k < 8; ++k) { S1 += red[k]; S2 += red[8 + k]; }
            float mu = S1 * (1.f / 1792.f);
            float var = S2 * (1.f / 1792.f) - mu * mu;
            red[16] = mu; red[17] = rsqrtf(var + EPSV);
        }
        __syncthreads();
        float mu = red[16], inv = red[17];
        #pragma unroll
        for (int k = 0; k < 7; ++k) {
            int v = t + k * 256;
            vals[k] = (vals[k] - mu) * inv * ln_w[v] + ln_b[v];
        }
    }
    __syncthreads();   // all phase-1 activation reads done; xbuf dies below

    // zero xpadA/shA/xpadB ([0,9216)) + stage w_res half 1 (overwrites vTw/xbuf)
    {
        float4 z4 = make_float4(0.f, 0.f, 0.f, 0.f);
        float4* z = (float4*)sm;
        for (int idx = t; idx < 2304; idx += 256) z[idx] = z4;
        for (int idx = t; idx < 4608; idx += 256) {
            int o = idx / 144, r = idx - o * 144;
            sm[WR2_OFF + r * 33 + o] = w_res[o * 288 + r];
        }
    }
    __syncthreads();
    {
        int c = t / 56, s = t - c * 56;
        #pragma unroll
        for (int k = 0; k < 7; ++k) {   // scatter LN output into xpadA + shifted shA
            int p = s >> 3, q = s & 7;
            sm[XPA_OFF + c * 108 + (p + 1) * 12 + (q + 1)] = vals[k];
            sm[SHA_OFF + c * 72 + (p + 1) * 8 + q] = vals[k];
            s += 32; c += 4; if (s >= 56) { s -= 56; ++c; }
        }
    }
    __syncthreads();

    // ============ Stage E: residual 3x3 conv 32->32 (+BN+ReLU+res) ============
    ull e[4] = {0,0,0,0};
    if (w < 7) conv16(e, sm + XPA_OFF, sm + SHA_OFF, sm + WR2_OFF, 33, lane, w);
    __syncthreads();
    for (int idx = t; idx < 4608; idx += 256) {    // stage w_res half 2
        int o = idx / 144, r = idx - o * 144;
        sm[WR2_OFF + r * 33 + o] = w_res[o * 288 + 144 + r];
    }
    __syncthreads();
    float er[8];
    if (w < 7) {
        conv16(e, sm + XPA_OFF + 16 * 108, sm + SHA_OFF + 16 * 72, sm + WR2_OFF, 33, lane, w);
        float sc = bnres_w[lane] * rsqrtf(bnres_v[lane] + EPSV);
        float bi = fmaf(b_res[lane], sc, bnres_b[lane] - bnres_m[lane] * sc);
        float r[8];
        up2(e[0],r[0],r[1]); up2(e[1],r[2],r[3]); up2(e[2],r[4],r[5]); up2(e[3],r[6],r[7]);
        const float* rs = sm + XPA_OFF + lane * 108 + (w + 1) * 12 + 1;
        #pragma unroll
        for (int q = 0; q < 8; ++q)
            er[q] = fmaxf(fmaf(r[q], sc, bi), 0.f) + rs[q];
    }
    __syncthreads();   // all shA reads done; shB may overwrite shA region

    // write stage-E results (xpadB + shB) and stage w1T/w2 concurrently
    if (w < 7) {
        float* db = sm + XPB_OFF + lane * 108 + (w + 1) * 12 + 1;
        float* sb = sm + SHB_OFF + lane * 72 + (w + 1) * 8;
        #pragma unroll
        for (int q = 0; q < 8; ++q) { db[q] = er[q]; sb[q] = er[q]; }
    }
    for (int idx = t; idx < 4608; idx += 256) {    // w1T two halves, stride 17
        int o = idx / 288, rr = idx - o * 288;
        int half = (rr >= 144) ? 1 : 0, rp = rr - half * 144;
        sm[WR2_OFF + half * 2448 + rp * 17 + o] = w1[idx];
    }
    if (t < 144) sm[W2_OFF + t] = w2[t];
    __syncthreads();

    // ============ Stage F: conv1 3x3 32->16 + BN + ReLU (lane halves split in-ch) ==
    if (w < 7) {
        int o16 = lane & 15, half = lane >> 4;
        ull f[4] = {0,0,0,0};
        conv16(f, sm + XPB_OFF + half * 1728, sm + SHB_OFF + half * 1152,
               sm + WR2_OFF + half * 2448, 17, o16, w);
        #pragma unroll
        for (int m = 0; m < 4; ++m) {
            ull other = __shfl_xor_sync(0xffffffffu, f[m], 16);
            f[m] = add2(f[m], other);
        }
        if (half == 0) {
            float sc = bn1_w[o16] * rsqrtf(bn1_v[o16] + EPSV);
            float bi = fmaf(b1[o16], sc, bn1_b[o16] - bn1_m[o16] * sc);
            float r[8];
            up2(f[0],r[0],r[1]); up2(f[1],r[2],r[3]); up2(f[2],r[4],r[5]); up2(f[3],r[6],r[7]);
            float* dst = sm + XPA_OFF + o16 * 108 + (w + 1) * 12 + 1;
            #pragma unroll
            for (int q = 0; q < 8; ++q) dst[q] = fmaxf(fmaf(r[q], sc, bi), 0.f);
        }
    }
    __syncthreads();

    // ============ Stage G: conv2 3x3 16->1 ============
    if (t < 56) {
        int p = t >> 3, q = t & 7;
        float acc2 = b2[0];
        #pragma unroll 4
        for (int i = 0; i < 16; ++i) {
            const float* xc = sm + XPA_OFF + i * 108 + p * 12 + q;
            const float* wg = sm + W2_OFF + i * 9;
            acc2 = fmaf(wg[0], xc[0],  acc2);
            acc2 = fmaf(wg[1], xc[1],  acc2);
            acc2 = fmaf(wg[2], xc[2],  acc2);
            acc2 = fmaf(wg[3], xc[12], acc2);
            acc2 = fmaf(wg[4], xc[13], acc2);
            acc2 = fmaf(wg[5], xc[14], acc2);
            acc2 = fmaf(wg[6], xc[24], acc2);
            acc2 = fmaf(wg[7], xc[25], acc2);
            acc2 = fmaf(wg[8], xc[26], acc2);
        }
        out[(size_t)b * 56 + t] = acc2;
    }
}

extern "C" void kernel_launch(void* const* d_in, const int* in_sizes, int n_in,
                              void* d_out, int out_size) {
    const float* mg      = (const float*)d_in[0];
    const float* w_cr    = (const float*)d_in[1];
    const float* b_cr    = (const float*)d_in[2];
    const float* bnr_w   = (const float*)d_in[3];
    const float* bnr_b   = (const float*)d_in[4];
    const float* bnr_m   = (const float*)d_in[5];
    const float* bnr_v   = (const float*)d_in[6];
    const float* q_w     = (const float*)d_in[7];
    const float* q_b     = (const float*)d_in[8];
    const float* k_w     = (const float*)d_in[9];
    const float* k_b     = (const float*)d_in[10];
    const float* v_w     = (const float*)d_in[11];
    const float* v_b     = (const float*)d_in[12];
    const float* gamma   = (const float*)d_in[13];
    const float* ln_w    = (const float*)d_in[14];
    const float* ln_b    = (const float*)d_in[15];
    const float* w_res   = (const float*)d_in[16];
    const float* b_res   = (const float*)d_in[17];
    const float* bnres_w = (const float*)d_in[18];
    const float* bnres_b = (const float*)d_in[19];
    const float* bnres_m = (const float*)d_in[20];
    const float* bnres_v = (const float*)d_in[21];
    const float* w1      = (const float*)d_in[22];
    const float* b1      = (const float*)d_in[23];
    const float* bn1_w   = (const float*)d_in[24];
    const float* bn1_b   = (const float*)d_in[25];
    const float* bn1_m   = (const float*)d_in[26];
    const float* bn1_v   = (const float*)d_in[27];
    const float* w2      = (const float*)d_in[28];
    const float* b2      = (const float*)d_in[29];

    int B = in_sizes[0] / 32768;
    size_t smem_bytes = SMEM_FLOATS * sizeof(float);   // 57344 = 56KB -> 4 CTAs/SM
    cudaFuncSetAttribute(occ_fused_kernel,
                         cudaFuncAttributeMaxDynamicSharedMemorySize, (int)smem_bytes);
    occ_fused_kernel<<<B, 256, smem_bytes>>>(
        mg, w_cr, b_cr, bnr_w, bnr_b, bnr_m, bnr_v,
        q_w, q_b, k_w, k_b, v_w, v_b, gamma, ln_w, ln_b,
        w_res, b_res, bnres_w, bnres_b, bnres_m, bnres_v,
        w1, b1, bn1_w, bn1_b, bn1_m, bn1_v, w2, b2,
        (float*)d_out);
}

// round 10
// speedup vs baseline: 1.0305x; 1.0305x over previous
#include <cuda_runtime.h>

#define EPSV 1e-5f
typedef unsigned long long ull;

// ---------------- shared memory layout (float offsets), 14336 floats = 56KB --
// Phase 1:
//   [0,7168)      pooled[128][56]
//     after stage B (pooled+wcrT dead): QT[4][60]@0, KT[4][60]@240,
//        VT[56][32]@480, S[56][60]@2272..5632, attnT[56][60]@5632..8992,
//        RED@8992..9024
//   [7168,11392)  wcrT[128][33]   (dead after stage B)
//   [11392,12416) vTw[32][32]
//   [12416,14336) xbuf[32][60]
// Phase 2:
//   [0,3456)      xpadA[32][9][12]
//   [3456,5760)   shA[32][9][8]
//   [3424,5760)   shB (aliases shA + 32-float XPA tail; halves @3424/4592)
//   [5760,9248)   xpadB 2 halves of [16][9][12], half stride 1744
//   [9248,14000)  wres half [144][33]=4752 ; later w1T 2x[144][17] @9248/11696
//   [14144,14288) w2
#define POOL_OFF 0
#define QT_OFF   0
#define KT_OFF   240
#define VT_OFF   480
#define S_OFF    2272
#define ATT_OFF  5632
#define RED_OFF  8992
#define WCRT_OFF 7168
#define VTW_OFF  11392
#define XBUF_OFF 12416

#define XPA_OFF  0
#define SHA_OFF  3456
#define SHB_OFF  3424
#define XPB_OFF  5760
#define WR2_OFF  9248
#define W2_OFF   14144
#define SMEM_FLOATS 14336

// ---------------- packed f32x2 helpers ----------------
__device__ __forceinline__ ull pk2(float x, float y) {
    ull r; asm("mov.b64 %0, {%1, %2};" : "=l"(r) : "f"(x), "f"(y)); return r;
}
__device__ __forceinline__ void up2(ull v, float& x, float& y) {
    asm("mov.b64 {%0, %1}, %2;" : "=f"(x), "=f"(y) : "l"(v));
}
__device__ __forceinline__ ull fma2(ull a, ull b, ull c) {
    ull r; asm("fma.rn.f32x2 %0, %1, %2, %3;" : "=l"(r) : "l"(a), "l"(b), "l"(c)); return r;
}
__device__ __forceinline__ ull add2(ull a, ull b) {
    ull r; asm("add.rn.f32x2 %0, %1, %2;" : "=l"(r) : "l"(a), "l"(b)); return r;
}

// 8-wide GEMM step: acc[4] += w * x[0..7], x warp-uniform (broadcast LDS.128)
// REQUIREMENT: x must be 16B-aligned (float offset % 4 == 0)
__device__ __forceinline__ void g8(ull acc[4], const float* __restrict__ x, float wv) {
    ulonglong2 A = *(const ulonglong2*)(x);
    ulonglong2 B = *(const ulonglong2*)(x + 4);
    ull wp = pk2(wv, wv);
    acc[0] = fma2(wp, A.x, acc[0]); acc[1] = fma2(wp, A.y, acc[1]);
    acc[2] = fma2(wp, B.x, acc[2]); acc[3] = fma2(wp, B.y, acc[3]);
}

// one 3-tap row application: 12 FFMA2 for 8 outputs
__device__ __forceinline__ void apply9(ull acc[4], const ull* __restrict__ W,
        const ulonglong2& E01, const ulonglong2& E23, ull E4,
        const ulonglong2& O01, const ulonglong2& O23) {
    acc[0] = fma2(W[0], E01.x, acc[0]); acc[1] = fma2(W[0], E01.y, acc[1]);
    acc[2] = fma2(W[0], E23.x, acc[2]); acc[3] = fma2(W[0], E23.y, acc[3]);
    acc[0] = fma2(W[1], O01.x, acc[0]); acc[1] = fma2(W[1], O01.y, acc[1]);
    acc[2] = fma2(W[1], O23.x, acc[2]); acc[3] = fma2(W[1], O23.y, acc[3]);
    acc[0] = fma2(W[2], E01.y, acc[0]); acc[1] = fma2(W[2], E23.x, acc[1]);
    acc[2] = fma2(W[2], E23.y, acc[2]); acc[3] = fma2(W[2], E4,    acc[3]);
}

// 3x3 conv over nch channels producing output rows p0 (and p0+1 if TWO).
// Weights for a channel are loaded once (9 taps) and shared by both rows.
template<bool TWO>
__device__ __forceinline__ void conv_pair(ull a0[4], ull a1[4],
    const float* __restrict__ xb, const float* __restrict__ sb,
    const float* __restrict__ wb, int ws, int o, int p0, int nch) {
    #pragma unroll 1
    for (int ch = 0; ch < nch; ++ch) {
        const float* wp = wb + ch * 9 * ws + o;
        ull W[9];
        #pragma unroll
        for (int k = 0; k < 9; ++k) { float wv = wp[k * ws]; W[k] = pk2(wv, wv); }
        const float* xrow = xb + ch * 108 + p0 * 12;
        const float* srow = sb + ch * 72  + p0 * 8;
        #pragma unroll
        for (int r = 0; r < (TWO ? 4 : 3); ++r) {
            ulonglong2 E01 = *(const ulonglong2*)(xrow + r * 12);
            ulonglong2 E23 = *(const ulonglong2*)(xrow + r * 12 + 4);
            ull        E4  = *(const ull*)(xrow + r * 12 + 8);
            ulonglong2 O01 = *(const ulonglong2*)(srow + r * 8);
            ulonglong2 O23 = *(const ulonglong2*)(srow + r * 8 + 4);
            if (r < 3)         apply9(a0, W + 3 * r,       E01, E23, E4, O01, O23);
            if (TWO && r >= 1) apply9(a1, W + 3 * (r - 1), E01, E23, E4, O01, O23);
        }
    }
}

__global__ void __launch_bounds__(256, 4) occ_fused_kernel(
    const float* __restrict__ mg,
    const float* __restrict__ w_cr, const float* __restrict__ b_cr,
    const float* __restrict__ bnr_w, const float* __restrict__ bnr_b,
    const float* __restrict__ bnr_m, const float* __restrict__ bnr_v,
    const float* __restrict__ q_w,  const float* __restrict__ q_b,
    const float* __restrict__ k_w,  const float* __restrict__ k_b,
    const float* __restrict__ v_w,  const float* __restrict__ v_b,
    const float* __restrict__ gamma,
    const float* __restrict__ ln_w, const float* __restrict__ ln_b,
    const float* __restrict__ w_res, const float* __restrict__ b_res,
    const float* __restrict__ bnres_w, const float* __restrict__ bnres_b,
    const float* __restrict__ bnres_m, const float* __restrict__ bnres_v,
    const float* __restrict__ w1,  const float* __restrict__ b1,
    const float* __restrict__ bn1_w, const float* __restrict__ bn1_b,
    const float* __restrict__ bn1_m, const float* __restrict__ bn1_v,
    const float* __restrict__ w2,  const float* __restrict__ b2,
    float* __restrict__ out)
{
    extern __shared__ float sm[];
    const int t = threadIdx.x;
    const int b = blockIdx.x;
    const int w = t >> 5;
    const int lane = t & 31;
    float* red = sm + RED_OFF;

    // ============ Stage A: adaptive pool 16x16 -> 7x8 + stage phase-1 weights ======
    {
        const float* in = mg + (size_t)b * 32768;
        int c = t / 56, s = t - c * 56;
        for (int idx = t; idx < 7168; idx += 256) {
            int p = s >> 3, q = s & 7;
            int r0 = (p * 147) >> 6;
            int r1 = ((p + 1) * 16 + 6) / 7;
            const float2* bp = (const float2*)(in + c * 256 + q * 2);
            float acc = 0.f;
            for (int r = r0; r < r1; ++r) { float2 v2 = bp[r * 8]; acc += v2.x + v2.y; }
            sm[POOL_OFF + idx] = acc * (0.5f / (float)(r1 - r0));
            s += 32; c += 4; if (s >= 56) { s -= 56; ++c; }
        }
        for (int idx = t; idx < 4096; idx += 256) {       // wcrT[c][o], stride 33
            int o = idx >> 7, cc = idx & 127;
            sm[WCRT_OFF + cc * 33 + o] = w_cr[idx];
        }
        for (int idx = t; idx < 1024; idx += 256) {       // vTw[in][o], stride 32
            int in2 = idx >> 5, o = idx & 31;
            sm[VTW_OFF + in2 * 32 + o] = v_w[o * 32 + in2];
        }
    }
    __syncthreads();

    // ============ Stage B: 1x1 128->32 + BN + ReLU. warp=p, lane=o ============
    if (w < 7) {
        ull a[4] = {0,0,0,0};
        const float* xb = sm + POOL_OFF + w * 8;
        const float* wc = sm + WCRT_OFF + lane;
        #pragma unroll 4
        for (int c = 0; c < 128; ++c)
            g8(a, xb + c * 56, wc[c * 33]);
        float sc = bnr_w[lane] * rsqrtf(bnr_v[lane] + EPSV);
        float bi = fmaf(b_cr[lane], sc, bnr_b[lane] - bnr_m[lane] * sc);
        float r[8];
        up2(a[0],r[0],r[1]); up2(a[1],r[2],r[3]); up2(a[2],r[4],r[5]); up2(a[3],r[6],r[7]);
        float* dst = sm + XBUF_OFF + lane * 60 + w * 8;
        #pragma unroll
        for (int q = 0; q < 8; ++q) dst[q] = fmaxf(fmaf(r[q], sc, bi), 0.f);
    }
    __syncthreads();

    // ============ Stage C1: v (warps 0-6), q & k (warp 7, weights via gmem) =======
    if (w < 7) {
        float bias = v_b[lane];
        ull a[4]; a[0]=a[1]=a[2]=a[3]=pk2(bias,bias);
        const float* xb = sm + XBUF_OFF + w * 8;
        const float* wv2p = sm + VTW_OFF + lane;
        #pragma unroll 4
        for (int in2 = 0; in2 < 32; ++in2)
            g8(a, xb + in2 * 60, wv2p[in2 * 32]);
        float r[8];
        up2(a[0],r[0],r[1]); up2(a[1],r[2],r[3]); up2(a[2],r[4],r[5]); up2(a[3],r[6],r[7]);
        #pragma unroll
        for (int q = 0; q < 8; ++q) sm[VT_OFF + (w * 8 + q) * 32 + lane] = r[q];
    } else if (lane < 28) {
        int d = lane / 7, p = lane - d * 7;
        const float* xb = sm + XBUF_OFF + p * 8;
        #pragma unroll
        for (int pass = 0; pass < 2; ++pass) {
            const float* W = (pass ? k_w : q_w) + d * 32;
            float bias = pass ? k_b[d] : q_b[d];
            ull a[4]; a[0]=a[1]=a[2]=a[3]=pk2(bias,bias);
            for (int in2 = 0; in2 < 32; ++in2) g8(a, xb + in2 * 60, __ldg(W + in2));
            float r[8];
            up2(a[0],r[0],r[1]); up2(a[1],r[2],r[3]); up2(a[2],r[4],r[5]); up2(a[3],r[6],r[7]);
            float* dst = sm + (pass ? KT_OFF : QT_OFF) + d * 60 + p * 8;
            #pragma unroll
            for (int q = 0; q < 8; ++q) dst[q] = r[q];
        }
    }
    __syncthreads();

    // ============ Stage C2: S[i][j] = sum_d q[d][i] k[d][j] ============
    if (w < 7) {
        int i0 = w * 8;
        #pragma unroll
        for (int seg = 0; seg < 2; ++seg) {
            int j = seg * 32 + lane;
            if (j < 56) {
                ull a[4] = {0,0,0,0};
                #pragma unroll
                for (int d = 0; d < 4; ++d)
                    g8(a, sm + QT_OFF + d * 60 + i0, sm[KT_OFF + d * 60 + j]);
                float r[8];
                up2(a[0],r[0],r[1]); up2(a[1],r[2],r[3]); up2(a[2],r[4],r[5]); up2(a[3],r[6],r[7]);
                #pragma unroll
                for (int q = 0; q < 8; ++q) sm[S_OFF + (i0 + q) * 60 + j] = r[q];
            }
        }
    }
    __syncthreads();

    // ============ softmax: 8 warps x 7 rows, shfl reductions, write attnT[j][i] ===
    // attnT stride 60 (MUST stay %4==0: C3 reads it with LDS.128)
    {
        int i0 = w * 7;
        #pragma unroll 1
        for (int rr = 0; rr < 7; ++rr) {
            int i = i0 + rr;
            const float* row = sm + S_OFF + i * 60;
            float v0 = row[lane];
            float v1 = (lane < 24) ? row[32 + lane] : -1e30f;
            float m = fmaxf(v0, v1);
            #pragma unroll
            for (int off = 16; off; off >>= 1)
                m = fmaxf(m, __shfl_xor_sync(0xffffffffu, m, off));
            float e0 = __expf(v0 - m);
            float e1 = (lane < 24) ? __expf(v1 - m) : 0.f;
            float ssum = e0 + e1;
            #pragma unroll
            for (int off = 16; off; off >>= 1)
                ssum += __shfl_xor_sync(0xffffffffu, ssum, off);
            float inv = 1.f / ssum;
            sm[ATT_OFF + lane * 60 + i] = e0 * inv;
            if (lane < 24) sm[ATT_OFF + (32 + lane) * 60 + i] = e1 * inv;
        }
    }
    __syncthreads();

    // ============ Stage C3: out[c][i] = sum_j v[j][c]*attnT[j][i]; x += gamma*out ==
    if (w < 7) {
        int i0 = w * 8;
        ull a[4] = {0,0,0,0};
        #pragma unroll 4
        for (int j = 0; j < 56; ++j)
            g8(a, sm + ATT_OFF + j * 60 + i0, sm[VT_OFF + j * 32 + lane]);
        float r[8];
        up2(a[0],r[0],r[1]); up2(a[1],r[2],r[3]); up2(a[2],r[4],r[5]); up2(a[3],r[6],r[7]);
        float g = gamma[0];
        float* xr = sm + XBUF_OFF + lane * 60 + i0;
        #pragma unroll
        for (int q = 0; q < 8; ++q) xr[q] = fmaf(g, r[q], xr[q]);
    }
    __syncthreads();

    // ============ Stage D: LayerNorm over 1792 ============
    float vals[7];
    {
        float s1 = 0.f, s2 = 0.f;
        int c = t / 56, s = t - c * 56;
        #pragma unroll
        for (int k = 0; k < 7; ++k) {
            float x = sm[XBUF_OFF + c * 60 + s];
            vals[k] = x; s1 += x; s2 = fmaf(x, x, s2);
            s += 32; c += 4; if (s >= 56) { s -= 56; ++c; }
        }
        #pragma unroll
        for (int off = 16; off; off >>= 1) {
            s1 += __shfl_xor_sync(0xffffffffu, s1, off);
            s2 += __shfl_xor_sync(0xffffffffu, s2, off);
        }
        if (lane == 0) { red[w] = s1; red[8 + w] = s2; }
        __syncthreads();
        if (t == 0) {
            float S1 = 0.f, S2 = 0.f;
            for (int k = 0; k < 8; ++k) { S1 += red[k]; S2 += red[8 + k]; }
            float mu = S1 * (1.f / 1792.f);
            float var = S2 * (1.f / 1792.f) - mu * mu;
            red[16] = mu; red[17] = rsqrtf(var + EPSV);
        }
        __syncthreads();
        float mu = red[16], inv = red[17];
        #pragma unroll
        for (int k = 0; k < 7; ++k) {
            int v = t + k * 256;
            vals[k] = (vals[k] - mu) * inv * ln_w[v] + ln_b[v];
        }
    }
    __syncthreads();   // all phase-1 activation reads done

    // zero phase-2 activation region [0,9248) + stage w_res half 1
    {
        float4 z4 = make_float4(0.f, 0.f, 0.f, 0.f);
        float4* z = (float4*)sm;
        for (int idx = t; idx < 2312; idx += 256) z[idx] = z4;
        for (int idx = t; idx < 4608; idx += 256) {
            int o = idx / 144, r = idx - o * 144;
            sm[WR2_OFF + r * 33 + o] = w_res[o * 288 + r];
        }
    }
    __syncthreads();
    {
        int c = t / 56, s = t - c * 56;
        #pragma unroll
        for (int k = 0; k < 7; ++k) {   // scatter LN output into xpadA + shifted shA
            int p = s >> 3, q = s & 7;
            sm[XPA_OFF + c * 108 + (p + 1) * 12 + (q + 1)] = vals[k];
            sm[SHA_OFF + c * 72 + (p + 1) * 8 + q] = vals[k];
            s += 32; c += 4; if (s >= 56) { s -= 56; ++c; }
        }
    }
    __syncthreads();

    // ============ Stage E: residual 3x3 conv 32->32 (+BN+ReLU+res), row pairs =====
    ull ea0[4] = {0,0,0,0}, ea1[4] = {0,0,0,0};
    const int p0 = (w < 3) ? 2 * w : 6;
    if (w < 3)       conv_pair<true >(ea0, ea1, sm + XPA_OFF, sm + SHA_OFF,
                                      sm + WR2_OFF, 33, lane, p0, 16);
    else if (w == 3) conv_pair<false>(ea0, ea1, sm + XPA_OFF, sm + SHA_OFF,
                                      sm + WR2_OFF, 33, lane, 6, 16);
    __syncthreads();
    for (int idx = t; idx < 4608; idx += 256) {    // stage w_res half 2
        int o = idx / 144, r = idx - o * 144;
        sm[WR2_OFF + r * 33 + o] = w_res[o * 288 + 144 + r];
    }
    __syncthreads();
    float er0[8], er1[8];
    if (w < 4) {
        if (w < 3) conv_pair<true >(ea0, ea1, sm + XPA_OFF + 16 * 108,
                                    sm + SHA_OFF + 16 * 72, sm + WR2_OFF, 33, lane, p0, 16);
        else       conv_pair<false>(ea0, ea1, sm + XPA_OFF + 16 * 108,
                                    sm + SHA_OFF + 16 * 72, sm + WR2_OFF, 33, lane, 6, 16);
        float sc = bnres_w[lane] * rsqrtf(bnres_v[lane] + EPSV);
        float bi = fmaf(b_res[lane], sc, bnres_b[lane] - bnres_m[lane] * sc);
        float r0[8];
        up2(ea0[0],r0[0],r0[1]); up2(ea0[1],r0[2],r0[3]);
        up2(ea0[2],r0[4],r0[5]); up2(ea0[3],r0[6],r0[7]);
        const float* rs0 = sm + XPA_OFF + lane * 108 + (p0 + 1) * 12 + 1;
        #pragma unroll
        for (int q = 0; q < 8; ++q) er0[q] = fmaxf(fmaf(r0[q], sc, bi), 0.f) + rs0[q];
        if (w < 3) {
            float r1[8];
            up2(ea1[0],r1[0],r1[1]); up2(ea1[1],r1[2],r1[3]);
            up2(ea1[2],r1[4],r1[5]); up2(ea1[3],r1[6],r1[7]);
            const float* rs1 = rs0 + 12;
            #pragma unroll
            for (int q = 0; q < 8; ++q) er1[q] = fmaxf(fmaf(r1[q], sc, bi), 0.f) + rs1[q];
        }
    }
    __syncthreads();   // all xpadA-residual & shA reads done; shB may alias now

    // write stage-E rows into xpadB/shB (bank-offset halves), zero shB pad rows,
    // and stage w1T/w2 concurrently
    if (w < 4) {
        int hoff = (lane >> 4) * 16;
        float* db0 = sm + XPB_OFF + lane * 108 + hoff + (p0 + 1) * 12 + 1;
        float* sb0 = sm + SHB_OFF + lane * 72 + hoff + (p0 + 1) * 8;
        #pragma unroll
        for (int q = 0; q < 8; ++q) { db0[q] = er0[q]; sb0[q] = er0[q]; }
        if (w < 3) {
            #pragma unroll
            for (int q = 0; q < 8; ++q) { db0[12 + q] = er1[q]; sb0[8 + q] = er1[q]; }
        }
    }
    {   // zero shB pad rows (rows 0 and 8 of each channel): 512 floats
        int idx = t;
        #pragma unroll
        for (int k = 0; k < 2; ++k) {
            int ch = idx >> 4, rem = idx & 15;
            int rowoff = (rem & 8) ? 64 : 0, q = rem & 7;
            sm[SHB_OFF + ch * 72 + (ch >> 4) * 16 + rowoff + q] = 0.f;
            idx += 256;
        }
    }
    for (int idx = t; idx < 4608; idx += 256) {    // w1T two halves, stride 17
        int o = idx / 288, rr = idx - o * 288;
        int half = (rr >= 144) ? 1 : 0, rp = rr - half * 144;
        sm[WR2_OFF + half * 2448 + rp * 17 + o] = w1[idx];
    }
    if (t < 144) sm[W2_OFF + t] = w2[t];
    __syncthreads();

    // ============ Stage F: conv1 3x3 32->16 + BN + ReLU, row pairs + lane halves ==
    if (w < 4) {
        int o16 = lane & 15, half = lane >> 4;
        const float* xb = sm + XPB_OFF + half * 1744;
        const float* sb = sm + SHB_OFF + half * 1168;
        const float* wb = sm + WR2_OFF + half * 2448;
        ull fa0[4] = {0,0,0,0}, fa1[4] = {0,0,0,0};
        if (w < 3) conv_pair<true >(fa0, fa1, xb, sb, wb, 17, o16, p0, 16);
        else       conv_pair<false>(fa0, fa1, xb, sb, wb, 17, o16, 6, 16);
        #pragma unroll
        for (int m = 0; m < 4; ++m) {
            fa0[m] = add2(fa0[m], __shfl_xor_sync(0xffffffffu, fa0[m], 16));
            fa1[m] = add2(fa1[m], __shfl_xor_sync(0xffffffffu, fa1[m], 16));
        }
        if (half == 0) {
            float sc = bn1_w[o16] * rsqrtf(bn1_v[o16] + EPSV);
            float bi = fmaf(b1[o16], sc, bn1_b[o16] - bn1_m[o16] * sc);
            float r0[8];
            up2(fa0[0],r0[0],r0[1]); up2(fa0[1],r0[2],r0[3]);
            up2(fa0[2],r0[4],r0[5]); up2(fa0[3],r0[6],r0[7]);
            float* dst = sm + XPA_OFF + o16 * 108 + (p0 + 1) * 12 + 1;
            #pragma unroll
            for (int q = 0; q < 8; ++q) dst[q] = fmaxf(fmaf(r0[q], sc, bi), 0.f);
            if (w < 3) {
                float r1[8];
                up2(fa1[0],r1[0],r1[1]); up2(fa1[1],r1[2],r1[3]);
                up2(fa1[2],r1[4],r1[5]); up2(fa1[3],r1[6],r1[7]);
                #pragma unroll
                for (int q = 0; q < 8; ++q) dst[12 + q] = fmaxf(fmaf(r1[q], sc, bi), 0.f);
            }
        }
    }
    __syncthreads();

    // ============ Stage G: conv2 3x3 16->1 ============
    if (t < 56) {
        int p = t >> 3, q = t & 7;
        float acc2 = b2[0];
        #pragma unroll 4
        for (int i = 0; i < 16; ++i) {
            const float* xc = sm + XPA_OFF + i * 108 + p * 12 + q;
            const float* wg = sm + W2_OFF + i * 9;
            acc2 = fmaf(wg[0], xc[0],  acc2);
            acc2 = fmaf(wg[1], xc[1],  acc2);
            acc2 = fmaf(wg[2], xc[2],  acc2);
            acc2 = fmaf(wg[3], xc[12], acc2);
            acc2 = fmaf(wg[4], xc[13], acc2);
            acc2 = fmaf(wg[5], xc[14], acc2);
            acc2 = fmaf(wg[6], xc[24], acc2);
            acc2 = fmaf(wg[7], xc[25], acc2);
            acc2 = fmaf(wg[8], xc[26], acc2);
        }
        out[(size_t)b * 56 + t] = acc2;
    }
}

extern "C" void kernel_launch(void* const* d_in, const int* in_sizes, int n_in,
                              void* d_out, int out_size) {
    const float* mg      = (const float*)d_in[0];
    const float* w_cr    = (const float*)d_in[1];
    const float* b_cr    = (const float*)d_in[2];
    const float* bnr_w   = (const float*)d_in[3];
    const float* bnr_b   = (const float*)d_in[4];
    const float* bnr_m   = (const float*)d_in[5];
    const float* bnr_v   = (const float*)d_in[6];
    const float* q_w     = (const float*)d_in[7];
    const float* q_b     = (const float*)d_in[8];
    const float* k_w     = (const float*)d_in[9];
    const float* k_b     = (const float*)d_in[10];
    const float* v_w     = (const float*)d_in[11];
    const float* v_b     = (const float*)d_in[12];
    const float* gamma   = (const float*)d_in[13];
    const float* ln_w    = (const float*)d_in[14];
    const float* ln_b    = (const float*)d_in[15];
    const float* w_res   = (const float*)d_in[16];
    const float* b_res   = (const float*)d_in[17];
    const float* bnres_w = (const float*)d_in[18];
    const float* bnres_b = (const float*)d_in[19];
    const float* bnres_m = (const float*)d_in[20];
    const float* bnres_v = (const float*)d_in[21];
    const float* w1      = (const float*)d_in[22];
    const float* b1      = (const float*)d_in[23];
    const float* bn1_w   = (const float*)d_in[24];
    const float* bn1_b   = (const float*)d_in[25];
    const float* bn1_m   = (const float*)d_in[26];
    const float* bn1_v   = (const float*)d_in[27];
    const float* w2      = (const float*)d_in[28];
    const float* b2      = (const float*)d_in[29];

    int B = in_sizes[0] / 32768;
    size_t smem_bytes = SMEM_FLOATS * sizeof(float);   // 56KB -> 4 CTAs/SM
    cudaFuncSetAttribute(occ_fused_kernel,
                         cudaFuncAttributeMaxDynamicSharedMemorySize, (int)smem_bytes);
    occ_fused_kernel<<<B, 256, smem_bytes>>>(
        mg, w_cr, b_cr, bnr_w, bnr_b, bnr_m, bnr_v,
        q_w, q_b, k_w, k_b, v_w, v_b, gamma, ln_w, ln_b,
        w_res, b_res, bnres_w, bnres_b, bnres_m, bnres_v,
        w1, b1, bn1_w, bn1_b, bn1_m, bn1_v, w2, b2,
        (float*)d_out);
}

// round 11
// speedup vs baseline: 1.0337x; 1.0031x over previous
#include <cuda_runtime.h>

#define EPSV 1e-5f
typedef unsigned long long ull;

// ---------------- shared memory layout (float offsets), 14336 floats = 56KB --
// Phase 1:
//   [0,7168)      pooled[128][56]
//     after stage B (pooled+wcrT dead): QT[4][60]@0, KT[4][60]@240,
//        VT[56][32]@480, S[56][60]@2272..5632, attnT[56][60]@5632..8992,
//        RED@8992..9024
//   [7168,11392)  wcrT[128][33]   (dead after stage B)
//   [11392,12416) vTw[32][32]
//   [12416,14336) xbuf[32][60]
// Phase 2:
//   [0,3456)      xpadA[32][9][12]
//   [3456,5760)   shA[32][9][8]
//   [3424,5760)   shB (aliases shA + 32-float XPA tail; halves @3424/4592)
//   [5760,9248)   xpadB 2 halves of [16][9][12], half stride 1744
//   [9248,14000)  wres half [144][33]=4752 ; later w1T 2x[144][17] @9248/11696
//   [14144,14288) w2
#define POOL_OFF 0
#define QT_OFF   0
#define KT_OFF   240
#define VT_OFF   480
#define S_OFF    2272
#define ATT_OFF  5632
#define RED_OFF  8992
#define WCRT_OFF 7168
#define VTW_OFF  11392
#define XBUF_OFF 12416

#define XPA_OFF  0
#define SHA_OFF  3456
#define SHB_OFF  3424
#define XPB_OFF  5760
#define WR2_OFF  9248
#define W2_OFF   14144
#define SMEM_FLOATS 14336

// ---------------- packed f32x2 helpers ----------------
__device__ __forceinline__ ull pk2(float x, float y) {
    ull r; asm("mov.b64 %0, {%1, %2};" : "=l"(r) : "f"(x), "f"(y)); return r;
}
__device__ __forceinline__ void up2(ull v, float& x, float& y) {
    asm("mov.b64 {%0, %1}, %2;" : "=f"(x), "=f"(y) : "l"(v));
}
__device__ __forceinline__ ull fma2(ull a, ull b, ull c) {
    ull r; asm("fma.rn.f32x2 %0, %1, %2, %3;" : "=l"(r) : "l"(a), "l"(b), "l"(c)); return r;
}
__device__ __forceinline__ ull add2(ull a, ull b) {
    ull r; asm("add.rn.f32x2 %0, %1, %2;" : "=l"(r) : "l"(a), "l"(b)); return r;
}

// 8-wide GEMM step: acc[4] += w * x[0..7], x warp-uniform (broadcast LDS.128)
// REQUIREMENT: x must be 16B-aligned (float offset % 4 == 0)
__device__ __forceinline__ void g8(ull acc[4], const float* __restrict__ x, float wv) {
    ulonglong2 A = *(const ulonglong2*)(x);
    ulonglong2 B = *(const ulonglong2*)(x + 4);
    ull wp = pk2(wv, wv);
    acc[0] = fma2(wp, A.x, acc[0]); acc[1] = fma2(wp, A.y, acc[1]);
    acc[2] = fma2(wp, B.x, acc[2]); acc[3] = fma2(wp, B.y, acc[3]);
}

// one 3-tap row application: 12 FFMA2 for 8 outputs
__device__ __forceinline__ void apply9(ull acc[4], const ull* __restrict__ W,
        const ulonglong2& E01, const ulonglong2& E23, ull E4,
        const ulonglong2& O01, const ulonglong2& O23) {
    acc[0] = fma2(W[0], E01.x, acc[0]); acc[1] = fma2(W[0], E01.y, acc[1]);
    acc[2] = fma2(W[0], E23.x, acc[2]); acc[3] = fma2(W[0], E23.y, acc[3]);
    acc[0] = fma2(W[1], O01.x, acc[0]); acc[1] = fma2(W[1], O01.y, acc[1]);
    acc[2] = fma2(W[1], O23.x, acc[2]); acc[3] = fma2(W[1], O23.y, acc[3]);
    acc[0] = fma2(W[2], E01.y, acc[0]); acc[1] = fma2(W[2], E23.x, acc[1]);
    acc[2] = fma2(W[2], E23.y, acc[2]); acc[3] = fma2(W[2], E4,    acc[3]);
}

// 3x3 conv over nch channels producing output rows p0 (and p0+1 if TWO).
// Weights for a channel are loaded once (9 taps) and shared by both rows.
template<bool TWO>
__device__ __forceinline__ void conv_pair(ull a0[4], ull a1[4],
    const float* __restrict__ xb, const float* __restrict__ sb,
    const float* __restrict__ wb, int ws, int o, int p0, int nch) {
    #pragma unroll 1
    for (int ch = 0; ch < nch; ++ch) {
        const float* wp = wb + ch * 9 * ws + o;
        ull W[9];
        #pragma unroll
        for (int k = 0; k < 9; ++k) { float wv = wp[k * ws]; W[k] = pk2(wv, wv); }
        const float* xrow = xb + ch * 108 + p0 * 12;
        const float* srow = sb + ch * 72  + p0 * 8;
        #pragma unroll
        for (int r = 0; r < (TWO ? 4 : 3); ++r) {
            ulonglong2 E01 = *(const ulonglong2*)(xrow + r * 12);
            ulonglong2 E23 = *(const ulonglong2*)(xrow + r * 12 + 4);
            ull        E4  = *(const ull*)(xrow + r * 12 + 8);
            ulonglong2 O01 = *(const ulonglong2*)(srow + r * 8);
            ulonglong2 O23 = *(const ulonglong2*)(srow + r * 8 + 4);
            if (r < 3)         apply9(a0, W + 3 * r,       E01, E23, E4, O01, O23);
            if (TWO && r >= 1) apply9(a1, W + 3 * (r - 1), E01, E23, E4, O01, O23);
        }
    }
}

__global__ void __launch_bounds__(256, 4) occ_fused_kernel(
    const float* __restrict__ mg,
    const float* __restrict__ w_cr, const float* __restrict__ b_cr,
    const float* __restrict__ bnr_w, const float* __restrict__ bnr_b,
    const float* __restrict__ bnr_m, const float* __restrict__ bnr_v,
    const float* __restrict__ q_w,  const float* __restrict__ q_b,
    const float* __restrict__ k_w,  const float* __restrict__ k_b,
    const float* __restrict__ v_w,  const float* __restrict__ v_b,
    const float* __restrict__ gamma,
    const float* __restrict__ ln_w, const float* __restrict__ ln_b,
    const float* __restrict__ w_res, const float* __restrict__ b_res,
    const float* __restrict__ bnres_w, const float* __restrict__ bnres_b,
    const float* __restrict__ bnres_m, const float* __restrict__ bnres_v,
    const float* __restrict__ w1,  const float* __restrict__ b1,
    const float* __restrict__ bn1_w, const float* __restrict__ bn1_b,
    const float* __restrict__ bn1_m, const float* __restrict__ bn1_v,
    const float* __restrict__ w2,  const float* __restrict__ b2,
    float* __restrict__ out)
{
    extern __shared__ float sm[];
    const int t = threadIdx.x;
    const int b = blockIdx.x;
    const int w = t >> 5;
    const int lane = t & 31;
    float* red = sm + RED_OFF;

    // ============ Stage A: adaptive pool 16x16 -> 7x8 + stage phase-1 weights ======
    {
        const float* in = mg + (size_t)b * 32768;
        int c = t / 56, s = t - c * 56;
        for (int idx = t; idx < 7168; idx += 256) {
            int p = s >> 3, q = s & 7;
            int r0 = (p * 147) >> 6;
            int r1 = ((p + 1) * 16 + 6) / 7;
            const float2* bp = (const float2*)(in + c * 256 + q * 2);
            float acc = 0.f;
            for (int r = r0; r < r1; ++r) { float2 v2 = bp[r * 8]; acc += v2.x + v2.y; }
            sm[POOL_OFF + idx] = acc * (0.5f / (float)(r1 - r0));
            s += 32; c += 4; if (s >= 56) { s -= 56; ++c; }
        }
        for (int idx = t; idx < 4096; idx += 256) {       // wcrT[c][o], stride 33
            int o = idx >> 7, cc = idx & 127;
            sm[WCRT_OFF + cc * 33 + o] = w_cr[idx];
        }
        for (int idx = t; idx < 1024; idx += 256) {       // vTw[in][o], stride 32
            int in2 = idx >> 5, o = idx & 31;
            sm[VTW_OFF + in2 * 32 + o] = v_w[o * 32 + in2];
        }
    }
    __syncthreads();

    // ============ Stage B: 1x1 128->32 + BN + ReLU. warp=p, lane=o ============
    if (w < 7) {
        ull a[4] = {0,0,0,0};
        const float* xb = sm + POOL_OFF + w * 8;
        const float* wc = sm + WCRT_OFF + lane;
        #pragma unroll 4
        for (int c = 0; c < 128; ++c)
            g8(a, xb + c * 56, wc[c * 33]);
        float sc = bnr_w[lane] * rsqrtf(bnr_v[lane] + EPSV);
        float bi = fmaf(b_cr[lane], sc, bnr_b[lane] - bnr_m[lane] * sc);
        float r[8];
        up2(a[0],r[0],r[1]); up2(a[1],r[2],r[3]); up2(a[2],r[4],r[5]); up2(a[3],r[6],r[7]);
        float* dst = sm + XBUF_OFF + lane * 60 + w * 8;
        #pragma unroll
        for (int q = 0; q < 8; ++q) dst[q] = fmaxf(fmaf(r[q], sc, bi), 0.f);
    }
    __syncthreads();

    // ============ Stage C1: v (warps 0-6), q & k (warp 7, weights via gmem) =======
    if (w < 7) {
        float bias = v_b[lane];
        ull a[4]; a[0]=a[1]=a[2]=a[3]=pk2(bias,bias);
        const float* xb = sm + XBUF_OFF + w * 8;
        const float* wv2p = sm + VTW_OFF + lane;
        #pragma unroll 4
        for (int in2 = 0; in2 < 32; ++in2)
            g8(a, xb + in2 * 60, wv2p[in2 * 32]);
        float r[8];
        up2(a[0],r[0],r[1]); up2(a[1],r[2],r[3]); up2(a[2],r[4],r[5]); up2(a[3],r[6],r[7]);
        #pragma unroll
        for (int q = 0; q < 8; ++q) sm[VT_OFF + (w * 8 + q) * 32 + lane] = r[q];
    } else if (lane < 28) {
        int d = lane / 7, p = lane - d * 7;
        const float* xb = sm + XBUF_OFF + p * 8;
        #pragma unroll
        for (int pass = 0; pass < 2; ++pass) {
            const float* W = (pass ? k_w : q_w) + d * 32;
            float bias = pass ? k_b[d] : q_b[d];
            ull a[4]; a[0]=a[1]=a[2]=a[3]=pk2(bias,bias);
            for (int in2 = 0; in2 < 32; ++in2) g8(a, xb + in2 * 60, __ldg(W + in2));
            float r[8];
            up2(a[0],r[0],r[1]); up2(a[1],r[2],r[3]); up2(a[2],r[4],r[5]); up2(a[3],r[6],r[7]);
            float* dst = sm + (pass ? KT_OFF : QT_OFF) + d * 60 + p * 8;
            #pragma unroll
            for (int q = 0; q < 8; ++q) dst[q] = r[q];
        }
    }
    __syncthreads();

    // ============ Stage C2: S[i][j] = sum_d q[d][i] k[d][j] ============
    if (w < 7) {
        int i0 = w * 8;
        #pragma unroll
        for (int seg = 0; seg < 2; ++seg) {
            int j = seg * 32 + lane;
            if (j < 56) {
                ull a[4] = {0,0,0,0};
                #pragma unroll
                for (int d = 0; d < 4; ++d)
                    g8(a, sm + QT_OFF + d * 60 + i0, sm[KT_OFF + d * 60 + j]);
                float r[8];
                up2(a[0],r[0],r[1]); up2(a[1],r[2],r[3]); up2(a[2],r[4],r[5]); up2(a[3],r[6],r[7]);
                #pragma unroll
                for (int q = 0; q < 8; ++q) sm[S_OFF + (i0 + q) * 60 + j] = r[q];
            }
        }
    }
    __syncthreads();

    // ============ softmax: 8 warps x 7 rows, shfl reductions, write attnT[j][i] ===
    // attnT stride 60 (MUST stay %4==0: C3 reads it with LDS.128)
    {
        int i0 = w * 7;
        #pragma unroll 1
        for (int rr = 0; rr < 7; ++rr) {
            int i = i0 + rr;
            const float* row = sm + S_OFF + i * 60;
            float v0 = row[lane];
            float v1 = (lane < 24) ? row[32 + lane] : -1e30f;
            float m = fmaxf(v0, v1);
            #pragma unroll
            for (int off = 16; off; off >>= 1)
                m = fmaxf(m, __shfl_xor_sync(0xffffffffu, m, off));
            float e0 = __expf(v0 - m);
            float e1 = (lane < 24) ? __expf(v1 - m) : 0.f;
            float ssum = e0 + e1;
            #pragma unroll
            for (int off = 16; off; off >>= 1)
                ssum += __shfl_xor_sync(0xffffffffu, ssum, off);
            float inv = 1.f / ssum;
            sm[ATT_OFF + lane * 60 + i] = e0 * inv;
            if (lane < 24) sm[ATT_OFF + (32 + lane) * 60 + i] = e1 * inv;
        }
    }
    __syncthreads();

    // ============ Stage C3: out[c][i] = sum_j v[j][c]*attnT[j][i]; x += gamma*out ==
    if (w < 7) {
        int i0 = w * 8;
        ull a[4] = {0,0,0,0};
        #pragma unroll 4
        for (int j = 0; j < 56; ++j)
            g8(a, sm + ATT_OFF + j * 60 + i0, sm[VT_OFF + j * 32 + lane]);
        float r[8];
        up2(a[0],r[0],r[1]); up2(a[1],r[2],r[3]); up2(a[2],r[4],r[5]); up2(a[3],r[6],r[7]);
        float g = gamma[0];
        float* xr = sm + XBUF_OFF + lane * 60 + i0;
        #pragma unroll
        for (int q = 0; q < 8; ++q) xr[q] = fmaf(g, r[q], xr[q]);
    }
    __syncthreads();

    // ============ Stage D: LayerNorm over 1792 ============
    float vals[7];
    {
        float s1 = 0.f, s2 = 0.f;
        int c = t / 56, s = t - c * 56;
        #pragma unroll
        for (int k = 0; k < 7; ++k) {
            float x = sm[XBUF_OFF + c * 60 + s];
            vals[k] = x; s1 += x; s2 = fmaf(x, x, s2);
            s += 32; c += 4; if (s >= 56) { s -= 56; ++c; }
        }
        #pragma unroll
        for (int off = 16; off; off >>= 1) {
            s1 += __shfl_xor_sync(0xffffffffu, s1, off);
            s2 += __shfl_xor_sync(0xffffffffu, s2, off);
        }
        if (lane == 0) { red[w] = s1; red[8 + w] = s2; }
        __syncthreads();
        if (t == 0) {
            float S1 = 0.f, S2 = 0.f;
            for (int k = 0; k < 8; ++k) { S1 += red[k]; S2 += red[8 + k]; }
            float mu = S1 * (1.f / 1792.f);
            float var = S2 * (1.f / 1792.f) - mu * mu;
            red[16] = mu; red[17] = rsqrtf(var + EPSV);
        }
        __syncthreads();
        float mu = red[16], inv = red[17];
        #pragma unroll
        for (int k = 0; k < 7; ++k) {
            int v = t + k * 256;
            vals[k] = (vals[k] - mu) * inv * ln_w[v] + ln_b[v];
        }
    }
    __syncthreads();   // all phase-1 activation reads done

    // zero phase-2 activation region [0,9248) + stage w_res half 1
    {
        float4 z4 = make_float4(0.f, 0.f, 0.f, 0.f);
        float4* z = (float4*)sm;
        for (int idx = t; idx < 2312; idx += 256) z[idx] = z4;
        for (int idx = t; idx < 4608; idx += 256) {
            int o = idx / 144, r = idx - o * 144;
            sm[WR2_OFF + r * 33 + o] = w_res[o * 288 + r];
        }
    }
    __syncthreads();
    {
        int c = t / 56, s = t - c * 56;
        #pragma unroll
        for (int k = 0; k < 7; ++k) {   // scatter LN output into xpadA + shifted shA
            int p = s >> 3, q = s & 7;
            sm[XPA_OFF + c * 108 + (p + 1) * 12 + (q + 1)] = vals[k];
            sm[SHA_OFF + c * 72 + (p + 1) * 8 + q] = vals[k];
            s += 32; c += 4; if (s >= 56) { s -= 56; ++c; }
        }
    }
    __syncthreads();

    // ============ Stage E: residual 3x3 conv 32->32 (+BN+ReLU+res), row pairs =====
    ull ea0[4] = {0,0,0,0}, ea1[4] = {0,0,0,0};
    const int p0 = (w < 3) ? 2 * w : 6;
    if (w < 3)       conv_pair<true >(ea0, ea1, sm + XPA_OFF, sm + SHA_OFF,
                                      sm + WR2_OFF, 33, lane, p0, 16);
    else if (w == 3) conv_pair<false>(ea0, ea1, sm + XPA_OFF, sm + SHA_OFF,
                                      sm + WR2_OFF, 33, lane, 6, 16);
    __syncthreads();
    for (int idx = t; idx < 4608; idx += 256) {    // stage w_res half 2
        int o = idx / 144, r = idx - o * 144;
        sm[WR2_OFF + r * 33 + o] = w_res[o * 288 + 144 + r];
    }
    __syncthreads();
    float er0[8], er1[8];
    if (w < 4) {
        if (w < 3) conv_pair<true >(ea0, ea1, sm + XPA_OFF + 16 * 108,
                                    sm + SHA_OFF + 16 * 72, sm + WR2_OFF, 33, lane, p0, 16);
        else       conv_pair<false>(ea0, ea1, sm + XPA_OFF + 16 * 108,
                                    sm + SHA_OFF + 16 * 72, sm + WR2_OFF, 33, lane, 6, 16);
        float sc = bnres_w[lane] * rsqrtf(bnres_v[lane] + EPSV);
        float bi = fmaf(b_res[lane], sc, bnres_b[lane] - bnres_m[lane] * sc);
        float r0[8];
        up2(ea0[0],r0[0],r0[1]); up2(ea0[1],r0[2],r0[3]);
        up2(ea0[2],r0[4],r0[5]); up2(ea0[3],r0[6],r0[7]);
        const float* rs0 = sm + XPA_OFF + lane * 108 + (p0 + 1) * 12 + 1;
        #pragma unroll
        for (int q = 0; q < 8; ++q) er0[q] = fmaxf(fmaf(r0[q], sc, bi), 0.f) + rs0[q];
        if (w < 3) {
            float r1[8];
            up2(ea1[0],r1[0],r1[1]); up2(ea1[1],r1[2],r1[3]);
            up2(ea1[2],r1[4],r1[5]); up2(ea1[3],r1[6],r1[7]);
            const float* rs1 = rs0 + 12;
            #pragma unroll
            for (int q = 0; q < 8; ++q) er1[q] = fmaxf(fmaf(r1[q], sc, bi), 0.f) + rs1[q];
        }
    }
    __syncthreads();   // all xpadA-residual & shA reads done; shB may alias now

    // write stage-E rows into xpadB/shB (bank-offset halves), zero shB pad rows,
    // and stage w1T/w2 concurrently
    if (w < 4) {
        int hoff = (lane >> 4) * 16;
        float* db0 = sm + XPB_OFF + lane * 108 + hoff + (p0 + 1) * 12 + 1;
        float* sb0 = sm + SHB_OFF + lane * 72 + hoff + (p0 + 1) * 8;
        #pragma unroll
        for (int q = 0; q < 8; ++q) { db0[q] = er0[q]; sb0[q] = er0[q]; }
        if (w < 3) {
            #pragma unroll
            for (int q = 0; q < 8; ++q) { db0[12 + q] = er1[q]; sb0[8 + q] = er1[q]; }
        }
    }
    {   // zero shB pad rows (rows 0 and 8 of each channel): 512 floats
        int idx = t;
        #pragma unroll
        for (int k = 0; k < 2; ++k) {
            int ch = idx >> 4, rem = idx & 15;
            int rowoff = (rem & 8) ? 64 : 0, q = rem & 7;
            sm[SHB_OFF + ch * 72 + (ch >> 4) * 16 + rowoff + q] = 0.f;
            idx += 256;
        }
    }
    for (int idx = t; idx < 4608; idx += 256) {    // w1T two halves, stride 17
        int o = idx / 288, rr = idx - o * 288;
        int half = (rr >= 144) ? 1 : 0, rp = rr - half * 144;
        sm[WR2_OFF + half * 2448 + rp * 17 + o] = w1[idx];
    }
    if (t < 144) sm[W2_OFF + t] = w2[t];
    __syncthreads();

    // ============ Stage F: conv1 3x3 32->16 + BN + ReLU, row pairs + lane halves ==
    if (w < 4) {
        int o16 = lane & 15, half = lane >> 4;
        const float* xb = sm + XPB_OFF + half * 1744;
        const float* sb = sm + SHB_OFF + half * 1168;
        const float* wb = sm + WR2_OFF + half * 2448;
        ull fa0[4] = {0,0,0,0}, fa1[4] = {0,0,0,0};
        if (w < 3) conv_pair<true >(fa0, fa1, xb, sb, wb, 17, o16, p0, 16);
        else       conv_pair<false>(fa0, fa1, xb, sb, wb, 17, o16, 6, 16);
        #pragma unroll
        for (int m = 0; m < 4; ++m) {
            fa0[m] = add2(fa0[m], __shfl_xor_sync(0xffffffffu, fa0[m], 16));
            fa1[m] = add2(fa1[m], __shfl_xor_sync(0xffffffffu, fa1[m], 16));
        }
        if (half == 0) {
            float sc = bn1_w[o16] * rsqrtf(bn1_v[o16] + EPSV);
            float bi = fmaf(b1[o16], sc, bn1_b[o16] - bn1_m[o16] * sc);
            float r0[8];
            up2(fa0[0],r0[0],r0[1]); up2(fa0[1],r0[2],r0[3]);
            up2(fa0[2],r0[4],r0[5]); up2(fa0[3],r0[6],r0[7]);
            float* dst = sm + XPA_OFF + o16 * 108 + (p0 + 1) * 12 + 1;
            #pragma unroll
            for (int q = 0; q < 8; ++q) dst[q] = fmaxf(fmaf(r0[q], sc, bi), 0.f);
            if (w < 3) {
                float r1[8];
                up2(fa1[0],r1[0],r1[1]); up2(fa1[1],r1[2],r1[3]);
                up2(fa1[2],r1[4],r1[5]); up2(fa1[3],r1[6],r1[7]);
                #pragma unroll
                for (int q = 0; q < 8; ++q) dst[12 + q] = fmaxf(fmaf(r1[q], sc, bi), 0.f);
            }
        }
    }
    __syncthreads();

    // ============ Stage G: conv2 3x3 16->1 ============
    if (t < 56) {
        int p = t >> 3, q = t & 7;
        float acc2 = b2[0];
        #pragma unroll 4
        for (int i = 0; i < 16; ++i) {
            const float* xc = sm + XPA_OFF + i * 108 + p * 12 + q;
            const float* wg = sm + W2_OFF + i * 9;
            acc2 = fmaf(wg[0], xc[0],  acc2);
            acc2 = fmaf(wg[1], xc[1],  acc2);
            acc2 = fmaf(wg[2], xc[2],  acc2);
            acc2 = fmaf(wg[3], xc[12], acc2);
            acc2 = fmaf(wg[4], xc[13], acc2);
            acc2 = fmaf(wg[5], xc[14], acc2);
            acc2 = fmaf(wg[6], xc[24], acc2);
            acc2 = fmaf(wg[7], xc[25], acc2);
            acc2 = fmaf(wg[8], xc[26], acc2);
        }
        out[(size_t)b * 56 + t] = acc2;
    }
}

extern "C" void kernel_launch(void* const* d_in, const int* in_sizes, int n_in,
                              void* d_out, int out_size) {
    const float* mg      = (const float*)d_in[0];
    const float* w_cr    = (const float*)d_in[1];
    const float* b_cr    = (const float*)d_in[2];
    const float* bnr_w   = (const float*)d_in[3];
    const float* bnr_b   = (const float*)d_in[4];
    const float* bnr_m   = (const float*)d_in[5];
    const float* bnr_v   = (const float*)d_in[6];
    const float* q_w     = (const float*)d_in[7];
    const float* q_b     = (const float*)d_in[8];
    const float* k_w     = (const float*)d_in[9];
    const float* k_b     = (const float*)d_in[10];
    const float* v_w     = (const float*)d_in[11];
    const float* v_b     = (const float*)d_in[12];
    const float* gamma   = (const float*)d_in[13];
    const float* ln_w    = (const float*)d_in[14];
    const float* ln_b    = (const float*)d_in[15];
    const float* w_res   = (const float*)d_in[16];
    const float* b_res   = (const float*)d_in[17];
    const float* bnres_w = (const float*)d_in[18];
    const float* bnres_b = (const float*)d_in[19];
    const float* bnres_m = (const float*)d_in[20];
    const float* bnres_v = (const float*)d_in[21];
    const float* w1      = (const float*)d_in[22];
    const float* b1      = (const float*)d_in[23];
    const float* bn1_w   = (const float*)d_in[24];
    const float* bn1_b   = (const float*)d_in[25];
    const float* bn1_m   = (const float*)d_in[26];
    const float* bn1_v   = (const float*)d_in[27];
    const float* w2      = (const float*)d_in[28];
    const float* b2      = (const float*)d_in[29];

    int B = in_sizes[0] / 32768;
    size_t smem_bytes = SMEM_FLOATS * sizeof(float);   // 56KB -> 4 CTAs/SM
    cudaFuncSetAttribute(occ_fused_kernel,
                         cudaFuncAttributeMaxDynamicSharedMemorySize, (int)smem_bytes);
    occ_fused_kernel<<<B, 256, smem_bytes>>>(
        mg, w_cr, b_cr, bnr_w, bnr_b, bnr_m, bnr_v,
        q_w, q_b, k_w, k_b, v_w, v_b, gamma, ln_w, ln_b,
        w_res, b_res, bnres_w, bnres_b, bnres_m, bnres_v,
        w1, b1, bn1_w, bn1_b, bn1_m, bn1_v, w2, b2,
        (float*)d_out);
}